// round 3
// baseline (speedup 1.0000x reference)
#include <cuda_runtime.h>
#include <cuda_bf16.h>

#define D 1024
#define THREADS 256          // 256 threads * 4 floats = 1024 = D
#define EPS 5e-05f

__global__ __launch_bounds__(THREADS)
void qlayernorm_kernel(const float* __restrict__ x,
                       const float* __restrict__ w,
                       const float* __restrict__ b,
                       float* __restrict__ out)
{
    const long long row = blockIdx.x;
    const float4* __restrict__ xr = reinterpret_cast<const float4*>(x + row * D);
    float4*       __restrict__ orow = reinterpret_cast<float4*>(out + row * D);
    const float4* __restrict__ wr = reinterpret_cast<const float4*>(w);
    const float4* __restrict__ br = reinterpret_cast<const float4*>(b);

    const int t = threadIdx.x;

    // Single pass over the row: keep the data in registers.
    float4 v = xr[t];
    float s  = v.x + v.y + v.z + v.w;
    float sq = v.x * v.x + v.y * v.y + v.z * v.z + v.w * v.w;

    // Warp reduction
    #pragma unroll
    for (int off = 16; off > 0; off >>= 1) {
        s  += __shfl_xor_sync(0xFFFFFFFFu, s,  off);
        sq += __shfl_xor_sync(0xFFFFFFFFu, sq, off);
    }

    __shared__ float sh_s[THREADS / 32];
    __shared__ float sh_q[THREADS / 32];
    const int warp = t >> 5;
    const int lane = t & 31;
    if (lane == 0) { sh_s[warp] = s; sh_q[warp] = sq; }
    __syncthreads();

    // Cross-warp reduction: every thread folds the 8 partials (cheap, no 2nd barrier).
    s = 0.f; sq = 0.f;
    #pragma unroll
    for (int i = 0; i < THREADS / 32; i++) { s += sh_s[i]; sq += sh_q[i]; }

    const float inv_d = 1.0f / (float)D;
    const float mean  = s * inv_d;
    const float var   = sq * inv_d - mean * mean;

    // Faithful replication of the reference's 4-step loop:
    //   _loop(inp, a) = (inp/a + a) * 0.5
    const float a  = var + EPS;
    const float l1 = (a  / a + a) * 0.5f;
    const float l2 = (l1 / a + a) * 0.5f;
    const float l3 = (l2 / a + a) * 0.5f;
    const float sd = (l3 / a + a) * 0.5f;
    const float rstd = 1.0f / sd;

    const float4 wv = wr[t];
    const float4 bv = br[t];

    float4 o;
    o.x = (v.x - mean) * rstd * wv.x + bv.x;
    o.y = (v.y - mean) * rstd * wv.y + bv.y;
    o.z = (v.z - mean) * rstd * wv.z + bv.z;
    o.w = (v.w - mean) * rstd * wv.w + bv.w;
    orow[t] = o;
}

extern "C" void kernel_launch(void* const* d_in, const int* in_sizes, int n_in,
                              void* d_out, int out_size)
{
    const float* x = (const float*)d_in[0];
    const float* w = (const float*)d_in[1];
    const float* b = (const float*)d_in[2];
    float* out = (float*)d_out;

    const int rows = in_sizes[0] / D;   // 4 * 8192 = 32768
    qlayernorm_kernel<<<rows, THREADS>>>(x, w, b, out);
}

// round 5
// speedup vs baseline: 1.1769x; 1.1769x over previous
#include <cuda_runtime.h>
#include <cuda_bf16.h>

#define D 1024
#define THREADS 256
#define WARPS_PER_CTA (THREADS / 32)
#define VEC 8               // float4 chunks per lane per row: D / 4 / 32 = 8
#define EPS 5e-05f

__global__ __launch_bounds__(THREADS, 2)
void qlayernorm_warp_kernel(const float* __restrict__ x,
                            const float* __restrict__ w,
                            const float* __restrict__ b,
                            float* __restrict__ out,
                            int rows)
{
    const int lane  = threadIdx.x & 31;
    const int warp  = threadIdx.x >> 5;
    const int gwarp = blockIdx.x * WARPS_PER_CTA + warp;
    const int total_warps = gridDim.x * WARPS_PER_CTA;

    // Lane -> column mapping is fixed across rows: cache weight/bias in registers once.
    const float4* __restrict__ w4 = reinterpret_cast<const float4*>(w);
    const float4* __restrict__ b4 = reinterpret_cast<const float4*>(b);
    float4 wv[VEC], bv[VEC];
    #pragma unroll
    for (int i = 0; i < VEC; i++) {
        wv[i] = w4[lane + 32 * i];
        bv[i] = b4[lane + 32 * i];
    }

    const float inv_d = 1.0f / (float)D;

    for (int row = gwarp; row < rows; row += total_warps) {
        const float4* __restrict__ xr =
            reinterpret_cast<const float4*>(x + (long long)row * D);
        float4* __restrict__ orow =
            reinterpret_cast<float4*>(out + (long long)row * D);

        // 8 independent LDG.128 per lane — deep MLP, row stays in registers.
        float4 v[VEC];
        #pragma unroll
        for (int i = 0; i < VEC; i++) v[i] = xr[lane + 32 * i];

        float s = 0.0f, sq = 0.0f;
        #pragma unroll
        for (int i = 0; i < VEC; i++) {
            s  += v[i].x + v[i].y + v[i].z + v[i].w;
            sq += v[i].x * v[i].x + v[i].y * v[i].y
                + v[i].z * v[i].z + v[i].w * v[i].w;
        }

        // Warp-only reduction: no shared memory, no barrier.
        #pragma unroll
        for (int off = 16; off > 0; off >>= 1) {
            s  += __shfl_xor_sync(0xFFFFFFFFu, s,  off);
            sq += __shfl_xor_sync(0xFFFFFFFFu, sq, off);
        }

        const float mean = s * inv_d;
        const float var  = sq * inv_d - mean * mean;

        // Reference's 4-step loop: _loop(inp,a) = (inp/a + a)*0.5.
        // a/a == 1.0 exactly; remaining divides by a -> multiply by rcp(a).
        const float a  = var + EPS;
        const float r  = __frcp_rn(a);
        const float l1 = (1.0f   + a) * 0.5f;
        const float l2 = (l1 * r + a) * 0.5f;
        const float l3 = (l2 * r + a) * 0.5f;
        const float sd = (l3 * r + a) * 0.5f;
        const float rstd = __frcp_rn(sd);

        #pragma unroll
        for (int i = 0; i < VEC; i++) {
            float4 o;
            o.x = (v[i].x - mean) * rstd * wv[i].x + bv[i].x;
            o.y = (v[i].y - mean) * rstd * wv[i].y + bv[i].y;
            o.z = (v[i].z - mean) * rstd * wv[i].z + bv[i].z;
            o.w = (v[i].w - mean) * rstd * wv[i].w + bv[i].w;
            orow[lane + 32 * i] = o;
        }
    }
}

extern "C" void kernel_launch(void* const* d_in, const int* in_sizes, int n_in,
                              void* d_out, int out_size)
{
    const float* x = (const float*)d_in[0];
    const float* w = (const float*)d_in[1];
    const float* b = (const float*)d_in[2];
    float* out = (float*)d_out;

    const int rows = in_sizes[0] / D;   // 32768 for B=4, S=8192

    // Persistent: 2 CTAs per SM (148 SMs), warps loop over rows.
    const int grid = 2 * 148;
    qlayernorm_warp_kernel<<<grid, THREADS>>>(x, w, b, out, rows);
}